// round 1
// baseline (speedup 1.0000x reference)
#include <cuda_runtime.h>
#include <math.h>

#define B_  16
#define T_  512
#define C_  256
#define H_  8
#define HST 32      // temporal head size
#define HSS 64      // spatial head size

#define N_BTC (B_*T_*C_)           // 2,097,152
#define N_FF  (B_*T_*4*C_)         // 8,388,608
#define N_SCT ((long long)B_*H_*T_*T_)  // 33,554,432
#define N_SCS ((long long)B_*H_*C_*C_)  // 8,388,608

// ---- scratch layout (floats) ----
#define O_h    0
#define O_q    (O_h    + N_BTC)
#define O_k    (O_q    + N_BTC)
#define O_v    (O_k    + N_BTC)
#define O_o    (O_v    + N_BTC)
#define O_x    (O_o    + N_BTC)
#define O_h2   (O_x    + N_BTC)
#define O_tout (O_h2   + N_BTC)
#define O_hs   (O_tout + N_BTC)
#define O_qs   (O_hs   + N_BTC)
#define O_ks   (O_qs   + N_BTC)
#define O_x2   (O_ks   + N_BTC)
#define O_h3   (O_x2   + N_BTC)
#define O_ff   (O_h3   + N_BTC)
#define O_scT  (O_ff   + N_FF)
#define O_scS  (O_scT  + N_SCT)
#define TOTAL_SCRATCH (O_scS + N_SCS)   // 77,594,624 floats ~ 310 MB

__device__ float g_buf[TOTAL_SCRATCH];

// ============================== LayerNorm ==================================
__global__ void ln_kernel(const float* __restrict__ x, float* __restrict__ y,
                          const float* __restrict__ w, const float* __restrict__ b,
                          int L) {
    long long base = (long long)blockIdx.x * L;
    int tid = threadIdx.x;
    float s = 0.f, s2 = 0.f;
    for (int i = tid; i < L; i += 256) {
        float v = x[base + i];
        s += v; s2 += v * v;
    }
    __shared__ float sh[64];
    #pragma unroll
    for (int o = 16; o > 0; o >>= 1) {
        s  += __shfl_down_sync(0xffffffffu, s,  o);
        s2 += __shfl_down_sync(0xffffffffu, s2, o);
    }
    int warp = tid >> 5, lane = tid & 31;
    if (lane == 0) { sh[warp] = s; sh[warp + 32] = s2; }
    __syncthreads();
    if (tid == 0) {
        float ts = 0.f, ts2 = 0.f;
        for (int i = 0; i < 8; i++) { ts += sh[i]; ts2 += sh[32 + i]; }
        float m = ts / (float)L;
        float var = ts2 / (float)L - m * m;
        sh[0] = m;
        sh[1] = rsqrtf(var + 1e-6f);
    }
    __syncthreads();
    float m = sh[0], r = sh[1];
    for (int i = tid; i < L; i += 256)
        y[base + i] = (x[base + i] - m) * r * w[i] + b[i];
}

// ============================== Softmax (row) ==============================
// In-place softmax over rows of length L (L <= 512), 256 threads.
__global__ void softmax_kernel(float* __restrict__ x, int L) {
    long long base = (long long)blockIdx.x * L;
    int tid = threadIdx.x;
    float v[2];
    #pragma unroll
    for (int c = 0; c < 2; c++) {
        int i = tid + c * 256;
        v[c] = (i < L) ? x[base + i] : -3.4e38f;
    }
    float mx = fmaxf(v[0], v[1]);
    __shared__ float sh[32];
    #pragma unroll
    for (int o = 16; o > 0; o >>= 1) mx = fmaxf(mx, __shfl_down_sync(0xffffffffu, mx, o));
    int warp = tid >> 5, lane = tid & 31;
    if (lane == 0) sh[warp] = mx;
    __syncthreads();
    if (tid == 0) {
        float m = sh[0];
        for (int i = 1; i < 8; i++) m = fmaxf(m, sh[i]);
        sh[0] = m;
    }
    __syncthreads();
    mx = sh[0];
    float sum = 0.f;
    #pragma unroll
    for (int c = 0; c < 2; c++) {
        int i = tid + c * 256;
        if (i < L) { v[c] = expf(v[c] - mx); sum += v[c]; }
    }
    __syncthreads();
    #pragma unroll
    for (int o = 16; o > 0; o >>= 1) sum += __shfl_down_sync(0xffffffffu, sum, o);
    if (lane == 0) sh[warp] = sum;
    __syncthreads();
    if (tid == 0) {
        float s = 0.f;
        for (int i = 0; i < 8; i++) s += sh[i];
        sh[0] = 1.f / s;
    }
    __syncthreads();
    float inv = sh[0];
    #pragma unroll
    for (int c = 0; c < 2; c++) {
        int i = tid + c * 256;
        if (i < L) x[base + i] = v[c] * inv;
    }
}

// ============================ Mean over heads ==============================
__global__ void mean_heads_kernel(const float* __restrict__ sc, float* __restrict__ out) {
    long long idx = (long long)blockIdx.x * 256 + threadIdx.x;
    const long long NN = (long long)B_ * C_ * C_;
    if (idx >= NN) return;
    long long b = idx / (C_ * C_);
    long long r = idx % (C_ * C_);
    float s = 0.f;
    #pragma unroll
    for (int h = 0; h < H_; h++)
        s += sc[(b * H_ + h) * (long long)(C_ * C_) + r];
    out[idx] = s * 0.125f;
}

// ============================== Batched GEMM ===============================
// C[m,n] = alpha * sum_k A[m,k] * B'[k,n]   (+bias[n]) (relu) (+res[m,n])
// flags: 1=relu, 2=causal mask (C[m,n]=-1e30 if n>m), 4=B stored NT as [N,K]
#define BM 64
#define BN 64
#define BK 16
#define FLAG_RELU   1
#define FLAG_CAUSAL 2
#define FLAG_NT     4

__global__ __launch_bounds__(256)
void gemm_kernel(const float* __restrict__ A, int lda, long long sAo, long long sAi, int nInner,
                 const float* __restrict__ Bm, int ldb, long long sBo, long long sBi,
                 float* __restrict__ Cm, int ldc, long long sCo, long long sCi,
                 int M, int N, int K, float alpha,
                 const float* __restrict__ bias,
                 const float* __restrict__ res, int ldres, long long sRo, long long sRi,
                 int flags) {
    __shared__ __align__(16) float As[BK][BM + 4];
    __shared__ __align__(16) float Bs[BK][BN + 4];

    int z  = blockIdx.z;
    int zo = z / nInner, zi = z % nInner;
    const float* Ab = A  + zo * sAo + zi * sAi;
    const float* Bb = Bm + zo * sBo + zi * sBi;
    float*       Cb = Cm + zo * sCo + zi * sCi;
    const float* Rb = res ? (res + zo * sRo + zi * sRi) : (const float*)0;

    int tid = threadIdx.x;
    int tx = tid & 15, ty = tid >> 4;
    int row0 = blockIdx.y * BM;
    int col0 = blockIdx.x * BN;

    float acc[4][4] = {};

    for (int k0 = 0; k0 < K; k0 += BK) {
        // load A tile (BMxBK) into As[k][m]
        #pragma unroll
        for (int i = 0; i < 4; i++) {
            int idx = tid + i * 256;
            int m  = idx >> 4;
            int kk = idx & 15;
            int gm = row0 + m, gk = k0 + kk;
            As[kk][m] = (gm < M && gk < K) ? Ab[(long long)gm * lda + gk] : 0.f;
        }
        // load B tile into Bs[k][n]
        if (flags & FLAG_NT) {
            #pragma unroll
            for (int i = 0; i < 4; i++) {
                int idx = tid + i * 256;
                int n  = idx >> 4;
                int kk = idx & 15;
                int gn = col0 + n, gk = k0 + kk;
                Bs[kk][n] = (gn < N && gk < K) ? Bb[(long long)gn * ldb + gk] : 0.f;
            }
        } else {
            #pragma unroll
            for (int i = 0; i < 4; i++) {
                int idx = tid + i * 256;
                int kk = idx >> 6;
                int n  = idx & 63;
                int gn = col0 + n, gk = k0 + kk;
                Bs[kk][n] = (gn < N && gk < K) ? Bb[(long long)gk * ldb + gn] : 0.f;
            }
        }
        __syncthreads();
        #pragma unroll
        for (int kk = 0; kk < BK; kk++) {
            float4 a4 = *reinterpret_cast<const float4*>(&As[kk][ty * 4]);
            float4 b4 = *reinterpret_cast<const float4*>(&Bs[kk][tx * 4]);
            float a[4] = {a4.x, a4.y, a4.z, a4.w};
            float b[4] = {b4.x, b4.y, b4.z, b4.w};
            #pragma unroll
            for (int i = 0; i < 4; i++)
                #pragma unroll
                for (int j = 0; j < 4; j++)
                    acc[i][j] += a[i] * b[j];
        }
        __syncthreads();
    }

    // epilogue
    #pragma unroll
    for (int i = 0; i < 4; i++) {
        int gm = row0 + ty * 4 + i;
        if (gm >= M) continue;
        #pragma unroll
        for (int j = 0; j < 4; j++) {
            int gn = col0 + tx * 4 + j;
            if (gn >= N) continue;
            float vOut = acc[i][j] * alpha;
            if (bias) vOut += bias[gn];
            if (flags & FLAG_RELU) vOut = fmaxf(vOut, 0.f);
            if (Rb) vOut += Rb[(long long)gm * ldres + gn];
            if ((flags & FLAG_CAUSAL) && gn > gm) vOut = -1e30f;
            Cb[(long long)gm * ldc + gn] = vOut;
        }
    }
}

static inline void gemm(const float* A, int lda, long long sAo, long long sAi,
                        const float* Bm, int ldb, long long sBo, long long sBi,
                        float* Cm, int ldc, long long sCo, long long sCi,
                        int M, int N, int K, int bOuter, int bInner,
                        float alpha, const float* bias,
                        const float* res, int ldres, long long sRo, long long sRi,
                        int flags) {
    dim3 grid((N + BN - 1) / BN, (M + BM - 1) / BM, bOuter * bInner);
    gemm_kernel<<<grid, 256>>>(A, lda, sAo, sAi, bInner,
                               Bm, ldb, sBo, sBi,
                               Cm, ldc, sCo, sCi,
                               M, N, K, alpha, bias, res, ldres, sRo, sRi, flags);
}

// ================================ Launch ===================================
extern "C" void kernel_launch(void* const* d_in, const int* in_sizes, int n_in,
                              void* d_out, int out_size) {
    const float* x_T     = (const float*)d_in[0];
    const float* x_S     = (const float*)d_in[1];
    const float* Wq_t    = (const float*)d_in[2];
    const float* Wk_t    = (const float*)d_in[3];
    const float* Wv_t    = (const float*)d_in[4];
    const float* Wo      = (const float*)d_in[5];
    const float* Wq_s    = (const float*)d_in[6];
    const float* Wk_s    = (const float*)d_in[7];
    const float* ff1_w1  = (const float*)d_in[8];
    const float* ff1_b1  = (const float*)d_in[9];
    const float* ff1_w2  = (const float*)d_in[10];
    const float* ff1_b2  = (const float*)d_in[11];
    const float* ff2_w1  = (const float*)d_in[12];
    const float* ff2_b1  = (const float*)d_in[13];
    const float* ff2_w2  = (const float*)d_in[14];
    const float* ff2_b2  = (const float*)d_in[15];
    const float* t_ln1_w = (const float*)d_in[16];
    const float* t_ln1_b = (const float*)d_in[17];
    const float* t_ln2_w = (const float*)d_in[18];
    const float* t_ln2_b = (const float*)d_in[19];
    const float* s_ln1_w = (const float*)d_in[20];
    const float* s_ln1_b = (const float*)d_in[21];
    const float* fus_ln_w= (const float*)d_in[22];
    const float* fus_ln_b= (const float*)d_in[23];

    float* out = (float*)d_out;                 // [B,T,C]
    float* sw  = out + (size_t)N_BTC;           // [B,C,C] spatial weights

    float* g = 0;
    cudaGetSymbolAddress((void**)&g, g_buf);
    float* h    = g + O_h;
    float* q    = g + O_q;
    float* k    = g + O_k;
    float* v    = g + O_v;
    float* ob   = g + O_o;
    float* xb   = g + O_x;
    float* h2   = g + O_h2;
    float* tout = g + O_tout;
    float* hs   = g + O_hs;
    float* qs   = g + O_qs;
    float* ks   = g + O_ks;
    float* x2b  = g + O_x2;
    float* h3   = g + O_h3;
    float* ffb  = g + O_ff;
    float* scT  = g + O_scT;
    float* scS  = g + O_scS;

    const long long TC = (long long)T_ * C_;
    const long long TT = (long long)T_ * T_;
    const long long CC = (long long)C_ * C_;

    // ---- temporal branch ----
    ln_kernel<<<B_ * T_, 256>>>(x_T, h, t_ln1_w, t_ln1_b, C_);

    gemm(h, C_, 0, 0, Wq_t, C_, 0, 0, q, C_, 0, 0, B_*T_, C_, C_, 1, 1,
         1.f, 0, 0, 0, 0, 0, FLAG_NT);
    gemm(h, C_, 0, 0, Wk_t, C_, 0, 0, k, C_, 0, 0, B_*T_, C_, C_, 1, 1,
         1.f, 0, 0, 0, 0, 0, FLAG_NT);
    gemm(h, C_, 0, 0, Wv_t, C_, 0, 0, v, C_, 0, 0, B_*T_, C_, C_, 1, 1,
         1.f, 0, 0, 0, 0, 0, FLAG_NT);

    // scores[b,h,t,s] = q . k / sqrt(32), causal mask
    gemm(q, C_, TC, HST, k, C_, TC, HST,
         scT, T_, (long long)H_*TT, TT,
         T_, T_, HST, B_, H_,
         0.1767766952966369f, 0, 0, 0, 0, 0, FLAG_NT | FLAG_CAUSAL);

    softmax_kernel<<<B_ * H_ * T_, 256>>>(scT, T_);

    // o = att @ v  (NN)
    gemm(scT, T_, (long long)H_*TT, TT, v, C_, TC, HST,
         ob, C_, TC, HST,
         T_, HST, T_, B_, H_,
         1.f, 0, 0, 0, 0, 0, 0);

    // x = x_T + o @ Wo^T
    gemm(ob, C_, 0, 0, Wo, C_, 0, 0, xb, C_, 0, 0, B_*T_, C_, C_, 1, 1,
         1.f, 0, x_T, C_, 0, 0, FLAG_NT);

    ln_kernel<<<B_ * T_, 256>>>(xb, h2, t_ln2_w, t_ln2_b, C_);

    gemm(h2, C_, 0, 0, ff1_w1, C_, 0, 0, ffb, 4*C_, 0, 0, B_*T_, 4*C_, C_, 1, 1,
         1.f, ff1_b1, 0, 0, 0, 0, FLAG_NT | FLAG_RELU);
    gemm(ffb, 4*C_, 0, 0, ff1_w2, 4*C_, 0, 0, tout, C_, 0, 0, B_*T_, C_, 4*C_, 1, 1,
         1.f, ff1_b2, xb, C_, 0, 0, FLAG_NT);

    // ---- spatial branch ----
    ln_kernel<<<B_ * C_, 256>>>(x_S, hs, s_ln1_w, s_ln1_b, T_);

    gemm(hs, T_, 0, 0, Wq_s, T_, 0, 0, qs, T_, 0, 0, B_*C_, T_, T_, 1, 1,
         1.f, 0, 0, 0, 0, 0, FLAG_NT);
    gemm(hs, T_, 0, 0, Wk_s, T_, 0, 0, ks, T_, 0, 0, B_*C_, T_, T_, 1, 1,
         1.f, 0, 0, 0, 0, 0, FLAG_NT);

    // sc[b,h,c,e] = qs . ks / 8
    gemm(qs, T_, (long long)C_*T_, HSS, ks, T_, (long long)C_*T_, HSS,
         scS, C_, (long long)H_*CC, CC,
         C_, C_, HSS, B_, H_,
         0.125f, 0, 0, 0, 0, 0, FLAG_NT);

    softmax_kernel<<<B_ * H_ * C_, 256>>>(scS, C_);
    mean_heads_kernel<<<(B_*C_*C_ + 255) / 256, 256>>>(scS, sw);

    // ---- fusion ----
    // x2 = tout + fused, fused[t,c] = sum_e tout[t,e] * sw[c,e]
    gemm(tout, C_, TC, 0, sw, C_, CC, 0,
         x2b, C_, TC, 0,
         T_, C_, C_, B_, 1,
         1.f, 0, tout, C_, TC, 0, FLAG_NT);

    ln_kernel<<<B_ * T_, 256>>>(x2b, h3, fus_ln_w, fus_ln_b, C_);

    gemm(h3, C_, 0, 0, ff2_w1, C_, 0, 0, ffb, 4*C_, 0, 0, B_*T_, 4*C_, C_, 1, 1,
         1.f, ff2_b1, 0, 0, 0, 0, FLAG_NT | FLAG_RELU);
    gemm(ffb, 4*C_, 0, 0, ff2_w2, 4*C_, 0, 0, out, C_, 0, 0, B_*T_, C_, 4*C_, 1, 1,
         1.f, ff2_b2, x2b, C_, 0, 0, FLAG_NT);
}

// round 2
// speedup vs baseline: 1.2081x; 1.2081x over previous
#include <cuda_runtime.h>
#include <math.h>

#define B_  16
#define T_  512
#define C_  256
#define H_  8
#define HST 32      // temporal head size
#define HSS 64      // spatial head size

#define N_BTC (B_*T_*C_)
#define N_FF  (B_*T_*4*C_)
#define N_SCT ((long long)B_*H_*T_*T_)
#define N_SCS ((long long)B_*H_*C_*C_)

#define O_h    0
#define O_q    (O_h    + N_BTC)
#define O_k    (O_q    + N_BTC)
#define O_v    (O_k    + N_BTC)
#define O_o    (O_v    + N_BTC)
#define O_x    (O_o    + N_BTC)
#define O_h2   (O_x    + N_BTC)
#define O_tout (O_h2   + N_BTC)
#define O_hs   (O_tout + N_BTC)
#define O_qs   (O_hs   + N_BTC)
#define O_ks   (O_qs   + N_BTC)
#define O_x2   (O_ks   + N_BTC)
#define O_h3   (O_x2   + N_BTC)
#define O_ff   (O_h3   + N_BTC)
#define O_scT  (O_ff   + N_FF)
#define O_scS  (O_scT  + N_SCT)
#define TOTAL_SCRATCH (O_scS + N_SCS)

__device__ float g_buf[TOTAL_SCRATCH];

// ============================== LayerNorm ==================================
__global__ void ln_kernel(const float* __restrict__ x, float* __restrict__ y,
                          const float* __restrict__ w, const float* __restrict__ b,
                          int L) {
    long long base = (long long)blockIdx.x * L;
    int tid = threadIdx.x;
    float s = 0.f, s2 = 0.f;
    for (int i = tid; i < L; i += 256) {
        float v = x[base + i];
        s += v; s2 += v * v;
    }
    __shared__ float sh[64];
    #pragma unroll
    for (int o = 16; o > 0; o >>= 1) {
        s  += __shfl_down_sync(0xffffffffu, s,  o);
        s2 += __shfl_down_sync(0xffffffffu, s2, o);
    }
    int warp = tid >> 5, lane = tid & 31;
    if (lane == 0) { sh[warp] = s; sh[warp + 32] = s2; }
    __syncthreads();
    if (tid == 0) {
        float ts = 0.f, ts2 = 0.f;
        for (int i = 0; i < 8; i++) { ts += sh[i]; ts2 += sh[32 + i]; }
        float m = ts / (float)L;
        float var = ts2 / (float)L - m * m;
        sh[0] = m;
        sh[1] = rsqrtf(var + 1e-6f);
    }
    __syncthreads();
    float m = sh[0], r = sh[1];
    for (int i = tid; i < L; i += 256)
        y[base + i] = (x[base + i] - m) * r * w[i] + b[i];
}

// ============================== Softmax (row) ==============================
__global__ void softmax_kernel(float* __restrict__ x, int L) {
    long long base = (long long)blockIdx.x * L;
    int tid = threadIdx.x;
    float v[2];
    #pragma unroll
    for (int c = 0; c < 2; c++) {
        int i = tid + c * 256;
        v[c] = (i < L) ? x[base + i] : -3.4e38f;
    }
    float mx = fmaxf(v[0], v[1]);
    __shared__ float sh[32];
    #pragma unroll
    for (int o = 16; o > 0; o >>= 1) mx = fmaxf(mx, __shfl_down_sync(0xffffffffu, mx, o));
    int warp = tid >> 5, lane = tid & 31;
    if (lane == 0) sh[warp] = mx;
    __syncthreads();
    if (tid == 0) {
        float m = sh[0];
        for (int i = 1; i < 8; i++) m = fmaxf(m, sh[i]);
        sh[0] = m;
    }
    __syncthreads();
    mx = sh[0];
    float sum = 0.f;
    #pragma unroll
    for (int c = 0; c < 2; c++) {
        int i = tid + c * 256;
        if (i < L) { v[c] = expf(v[c] - mx); sum += v[c]; }
    }
    __syncthreads();
    #pragma unroll
    for (int o = 16; o > 0; o >>= 1) sum += __shfl_down_sync(0xffffffffu, sum, o);
    if (lane == 0) sh[warp] = sum;
    __syncthreads();
    if (tid == 0) {
        float s = 0.f;
        for (int i = 0; i < 8; i++) s += sh[i];
        sh[0] = 1.f / s;
    }
    __syncthreads();
    float inv = sh[0];
    #pragma unroll
    for (int c = 0; c < 2; c++) {
        int i = tid + c * 256;
        if (i < L) x[base + i] = v[c] * inv;
    }
}

// ============================ Mean over heads ==============================
__global__ void mean_heads_kernel(const float* __restrict__ sc, float* __restrict__ out) {
    long long idx = (long long)blockIdx.x * 256 + threadIdx.x;
    const long long NN = (long long)B_ * C_ * C_;
    if (idx >= NN) return;
    long long b = idx / (C_ * C_);
    long long r = idx % (C_ * C_);
    float s = 0.f;
    #pragma unroll
    for (int h = 0; h < H_; h++)
        s += sc[(b * H_ + h) * (long long)(C_ * C_) + r];
    out[idx] = s * 0.125f;
}

// ======================= Tensor-core GEMM (3xTF32) =========================
#define FLAG_RELU   1
#define FLAG_CAUSAL 2
#define FLAG_NT     4

__device__ __forceinline__ unsigned f2tf(float f) {
    unsigned u;
    asm("cvt.rna.tf32.f32 %0, %1;" : "=r"(u) : "f"(f));
    return u;
}
__device__ __forceinline__ void split_tf32(float f, unsigned &hi, unsigned &lo) {
    hi = f2tf(f);
    float r = f - __uint_as_float(hi);
    lo = f2tf(r);
}
__device__ __forceinline__ void mma8(float* c, const unsigned* a, const unsigned* b) {
    asm volatile("mma.sync.aligned.m16n8k8.row.col.f32.tf32.tf32.f32 "
        "{%0,%1,%2,%3}, {%4,%5,%6,%7}, {%8,%9}, {%0,%1,%2,%3};"
        : "+f"(c[0]), "+f"(c[1]), "+f"(c[2]), "+f"(c[3])
        : "r"(a[0]), "r"(a[1]), "r"(a[2]), "r"(a[3]), "r"(b[0]), "r"(b[1]));
}

// C = alpha * A @ B' (+bias)(relu)(+res)(causal). Full tiles assumed:
// M % 128 == 0, N % BN == 0, K % 32 == 0.  flags&FLAG_NT: B is [N,K], else [K,N].
template<int BN, int WN>
__global__ __launch_bounds__(128 * WN)
void mma_gemm(const float* __restrict__ A, int lda, long long sAo, long long sAi, int nInner,
              const float* __restrict__ Bm, int ldb, long long sBo, long long sBi,
              float* __restrict__ Cm, int ldc, long long sCo, long long sCi,
              int K, float alpha,
              const float* __restrict__ bias,
              const float* __restrict__ res, int ldres, long long sRo, long long sRi,
              int flags) {
    constexpr int BM = 128, BK = 32;
    constexpr int THREADS = 128 * WN;
    constexpr int WNT = BN / WN;        // n extent per warp
    constexpr int NJ  = WNT / 8;        // n8 mma tiles per warp

    __shared__ __align__(16) float As[BK][BM + 8];
    __shared__ __align__(16) float Bs[BK][BN + 8];

    int z  = blockIdx.z;
    int zo = z / nInner, zi = z % nInner;
    const float* Ab = A  + zo * sAo + zi * sAi;
    const float* Bb = Bm + zo * sBo + zi * sBi;
    float*       Cb = Cm + zo * sCo + zi * sCi;
    const float* Rb = res ? (res + zo * sRo + zi * sRi) : (const float*)0;

    int tid = threadIdx.x, lane = tid & 31, wid = tid >> 5;
    int wm = wid & 3, wn = wid >> 2;
    int row0 = blockIdx.y * BM;
    int col0 = blockIdx.x * BN;

    float acc[2][NJ][4];
    #pragma unroll
    for (int i = 0; i < 2; i++)
        #pragma unroll
        for (int j = 0; j < NJ; j++)
            #pragma unroll
            for (int e = 0; e < 4; e++) acc[i][j][e] = 0.f;

    int r = lane >> 2, cq = lane & 3;

    for (int k0 = 0; k0 < K; k0 += BK) {
        // ---- load A tile: [BM][BK] row-major gmem -> As[k][m] ----
        #pragma unroll
        for (int i = 0; i < 8 / WN; i++) {
            int idx = tid + i * THREADS;          // 0..1023
            int m = idx >> 3;
            int kk = (idx & 7) * 4;
            float4 vA = *reinterpret_cast<const float4*>(
                Ab + (long long)(row0 + m) * lda + k0 + kk);
            As[kk][m] = vA.x; As[kk+1][m] = vA.y; As[kk+2][m] = vA.z; As[kk+3][m] = vA.w;
        }
        // ---- load B tile ----
        if (flags & FLAG_NT) {
            #pragma unroll
            for (int i = 0; i < (BN * 8) / THREADS; i++) {
                int idx = tid + i * THREADS;
                int n = idx >> 3;
                int kk = (idx & 7) * 4;
                float4 vB = *reinterpret_cast<const float4*>(
                    Bb + (long long)(col0 + n) * ldb + k0 + kk);
                Bs[kk][n] = vB.x; Bs[kk+1][n] = vB.y; Bs[kk+2][n] = vB.z; Bs[kk+3][n] = vB.w;
            }
        } else {
            #pragma unroll
            for (int i = 0; i < (BN * 8) / THREADS; i++) {
                int idx = tid + i * THREADS;
                int kk = idx / (BN / 4);
                int n4 = idx % (BN / 4);
                float4 vB = *reinterpret_cast<const float4*>(
                    Bb + (long long)(k0 + kk) * ldb + col0 + n4 * 4);
                *reinterpret_cast<float4*>(&Bs[kk][n4 * 4]) = vB;
            }
        }
        __syncthreads();

        #pragma unroll
        for (int k8 = 0; k8 < BK / 8; k8++) {
            // B fragments
            unsigned bh[NJ][2], bl[NJ][2];
            #pragma unroll
            for (int j = 0; j < NJ; j++) {
                int ncol = wn * WNT + j * 8 + r;
                float b0 = Bs[k8 * 8 + cq][ncol];
                float b1 = Bs[k8 * 8 + cq + 4][ncol];
                split_tf32(b0, bh[j][0], bl[j][0]);
                split_tf32(b1, bh[j][1], bl[j][1]);
            }
            #pragma unroll
            for (int im = 0; im < 2; im++) {
                unsigned ah[4], al[4];
                int mrow = wm * 32 + im * 16 + r;
                float a0 = As[k8 * 8 + cq][mrow];
                float a1 = As[k8 * 8 + cq][mrow + 8];
                float a2 = As[k8 * 8 + cq + 4][mrow];
                float a3 = As[k8 * 8 + cq + 4][mrow + 8];
                split_tf32(a0, ah[0], al[0]);
                split_tf32(a1, ah[1], al[1]);
                split_tf32(a2, ah[2], al[2]);
                split_tf32(a3, ah[3], al[3]);
                #pragma unroll
                for (int j = 0; j < NJ; j++) {
                    mma8(acc[im][j], al, bh[j]);   // lo*hi
                    mma8(acc[im][j], ah, bl[j]);   // hi*lo
                    mma8(acc[im][j], ah, bh[j]);   // hi*hi
                }
            }
        }
        __syncthreads();
    }

    // ---- epilogue ----
    #pragma unroll
    for (int im = 0; im < 2; im++) {
        #pragma unroll
        for (int j = 0; j < NJ; j++) {
            int gm0 = row0 + wm * 32 + im * 16 + r;
            int gn  = col0 + wn * WNT + j * 8 + cq * 2;
            #pragma unroll
            for (int half = 0; half < 2; half++) {
                int gm = gm0 + half * 8;
                float v0 = acc[im][j][half * 2 + 0] * alpha;
                float v1 = acc[im][j][half * 2 + 1] * alpha;
                if (bias) { v0 += bias[gn]; v1 += bias[gn + 1]; }
                if (flags & FLAG_RELU) { v0 = fmaxf(v0, 0.f); v1 = fmaxf(v1, 0.f); }
                if (Rb) {
                    const float* rp = Rb + (long long)gm * ldres + gn;
                    v0 += rp[0]; v1 += rp[1];
                }
                if (flags & FLAG_CAUSAL) {
                    if (gn > gm)     v0 = -1e30f;
                    if (gn + 1 > gm) v1 = -1e30f;
                }
                float2 st; st.x = v0; st.y = v1;
                *reinterpret_cast<float2*>(Cb + (long long)gm * ldc + gn) = st;
            }
        }
    }
}

static inline void gemm(const float* A, int lda, long long sAo, long long sAi,
                        const float* Bm, int ldb, long long sBo, long long sBi,
                        float* Cm, int ldc, long long sCo, long long sCi,
                        int M, int N, int K, int bOuter, int bInner,
                        float alpha, const float* bias,
                        const float* res, int ldres, long long sRo, long long sRi,
                        int flags) {
    if (N == 32) {
        dim3 grid(1, M / 128, bOuter * bInner);
        mma_gemm<32, 1><<<grid, 128>>>(A, lda, sAo, sAi, bInner,
                                       Bm, ldb, sBo, sBi, Cm, ldc, sCo, sCi,
                                       K, alpha, bias, res, ldres, sRo, sRi, flags);
    } else {
        dim3 grid(N / 128, M / 128, bOuter * bInner);
        mma_gemm<128, 2><<<grid, 256>>>(A, lda, sAo, sAi, bInner,
                                        Bm, ldb, sBo, sBi, Cm, ldc, sCo, sCi,
                                        K, alpha, bias, res, ldres, sRo, sRi, flags);
    }
}

// ================================ Launch ===================================
extern "C" void kernel_launch(void* const* d_in, const int* in_sizes, int n_in,
                              void* d_out, int out_size) {
    const float* x_T     = (const float*)d_in[0];
    const float* x_S     = (const float*)d_in[1];
    const float* Wq_t    = (const float*)d_in[2];
    const float* Wk_t    = (const float*)d_in[3];
    const float* Wv_t    = (const float*)d_in[4];
    const float* Wo      = (const float*)d_in[5];
    const float* Wq_s    = (const float*)d_in[6];
    const float* Wk_s    = (const float*)d_in[7];
    const float* ff1_w1  = (const float*)d_in[8];
    const float* ff1_b1  = (const float*)d_in[9];
    const float* ff1_w2  = (const float*)d_in[10];
    const float* ff1_b2  = (const float*)d_in[11];
    const float* ff2_w1  = (const float*)d_in[12];
    const float* ff2_b1  = (const float*)d_in[13];
    const float* ff2_w2  = (const float*)d_in[14];
    const float* ff2_b2  = (const float*)d_in[15];
    const float* t_ln1_w = (const float*)d_in[16];
    const float* t_ln1_b = (const float*)d_in[17];
    const float* t_ln2_w = (const float*)d_in[18];
    const float* t_ln2_b = (const float*)d_in[19];
    const float* s_ln1_w = (const float*)d_in[20];
    const float* s_ln1_b = (const float*)d_in[21];
    const float* fus_ln_w= (const float*)d_in[22];
    const float* fus_ln_b= (const float*)d_in[23];

    float* out = (float*)d_out;                 // [B,T,C]
    float* sw  = out + (size_t)N_BTC;           // [B,C,C]

    float* g = 0;
    cudaGetSymbolAddress((void**)&g, g_buf);
    float* h    = g + O_h;
    float* q    = g + O_q;
    float* k    = g + O_k;
    float* v    = g + O_v;
    float* ob   = g + O_o;
    float* xb   = g + O_x;
    float* h2   = g + O_h2;
    float* tout = g + O_tout;
    float* hs   = g + O_hs;
    float* qs   = g + O_qs;
    float* ks   = g + O_ks;
    float* x2b  = g + O_x2;
    float* h3   = g + O_h3;
    float* ffb  = g + O_ff;
    float* scT  = g + O_scT;
    float* scS  = g + O_scS;

    const long long TC = (long long)T_ * C_;
    const long long TT = (long long)T_ * T_;
    const long long CC = (long long)C_ * C_;

    // ---- temporal branch ----
    ln_kernel<<<B_ * T_, 256>>>(x_T, h, t_ln1_w, t_ln1_b, C_);

    gemm(h, C_, 0, 0, Wq_t, C_, 0, 0, q, C_, 0, 0, B_*T_, C_, C_, 1, 1,
         1.f, 0, 0, 0, 0, 0, FLAG_NT);
    gemm(h, C_, 0, 0, Wk_t, C_, 0, 0, k, C_, 0, 0, B_*T_, C_, C_, 1, 1,
         1.f, 0, 0, 0, 0, 0, FLAG_NT);
    gemm(h, C_, 0, 0, Wv_t, C_, 0, 0, v, C_, 0, 0, B_*T_, C_, C_, 1, 1,
         1.f, 0, 0, 0, 0, 0, FLAG_NT);

    // scores[b,h,t,s] = q . k / sqrt(32), causal mask
    gemm(q, C_, TC, HST, k, C_, TC, HST,
         scT, T_, (long long)H_*TT, TT,
         T_, T_, HST, B_, H_,
         0.1767766952966369f, 0, 0, 0, 0, 0, FLAG_NT | FLAG_CAUSAL);

    softmax_kernel<<<B_ * H_ * T_, 256>>>(scT, T_);

    // o = att @ v  (NN, N=32)
    gemm(scT, T_, (long long)H_*TT, TT, v, C_, TC, HST,
         ob, C_, TC, HST,
         T_, HST, T_, B_, H_,
         1.f, 0, 0, 0, 0, 0, 0);

    // x = x_T + o @ Wo^T
    gemm(ob, C_, 0, 0, Wo, C_, 0, 0, xb, C_, 0, 0, B_*T_, C_, C_, 1, 1,
         1.f, 0, x_T, C_, 0, 0, FLAG_NT);

    ln_kernel<<<B_ * T_, 256>>>(xb, h2, t_ln2_w, t_ln2_b, C_);

    gemm(h2, C_, 0, 0, ff1_w1, C_, 0, 0, ffb, 4*C_, 0, 0, B_*T_, 4*C_, C_, 1, 1,
         1.f, ff1_b1, 0, 0, 0, 0, FLAG_NT | FLAG_RELU);
    gemm(ffb, 4*C_, 0, 0, ff1_w2, 4*C_, 0, 0, tout, C_, 0, 0, B_*T_, C_, 4*C_, 1, 1,
         1.f, ff1_b2, xb, C_, 0, 0, FLAG_NT);

    // ---- spatial branch ----
    ln_kernel<<<B_ * C_, 256>>>(x_S, hs, s_ln1_w, s_ln1_b, T_);

    gemm(hs, T_, 0, 0, Wq_s, T_, 0, 0, qs, T_, 0, 0, B_*C_, T_, T_, 1, 1,
         1.f, 0, 0, 0, 0, 0, FLAG_NT);
    gemm(hs, T_, 0, 0, Wk_s, T_, 0, 0, ks, T_, 0, 0, B_*C_, T_, T_, 1, 1,
         1.f, 0, 0, 0, 0, 0, FLAG_NT);

    // sc[b,h,c,e] = qs . ks / 8
    gemm(qs, T_, (long long)C_*T_, HSS, ks, T_, (long long)C_*T_, HSS,
         scS, C_, (long long)H_*CC, CC,
         C_, C_, HSS, B_, H_,
         0.125f, 0, 0, 0, 0, 0, FLAG_NT);

    softmax_kernel<<<B_ * H_ * C_, 256>>>(scS, C_);
    mean_heads_kernel<<<(B_*C_*C_ + 255) / 256, 256>>>(scS, sw);

    // ---- fusion ----
    gemm(tout, C_, TC, 0, sw, C_, CC, 0,
         x2b, C_, TC, 0,
         T_, C_, C_, B_, 1,
         1.f, 0, tout, C_, TC, 0, FLAG_NT);

    ln_kernel<<<B_ * T_, 256>>>(x2b, h3, fus_ln_w, fus_ln_b, C_);

    gemm(h3, C_, 0, 0, ff2_w1, C_, 0, 0, ffb, 4*C_, 0, 0, B_*T_, 4*C_, C_, 1, 1,
         1.f, ff2_b1, 0, 0, 0, 0, FLAG_NT | FLAG_RELU);
    gemm(ffb, 4*C_, 0, 0, ff2_w2, 4*C_, 0, 0, out, C_, 0, 0, B_*T_, C_, 4*C_, 1, 1,
         1.f, ff2_b2, x2b, C_, 0, 0, FLAG_NT);
}

// round 3
// speedup vs baseline: 1.8699x; 1.5479x over previous
#include <cuda_runtime.h>
#include <cuda_bf16.h>
#include <math.h>

#define B_  16
#define T_  512
#define C_  256
#define H_  8
#define HST 32
#define HSS 64

#define N_BTC (B_*T_*C_)
#define N_FF  (B_*T_*4*C_)
#define N_SCT ((long long)B_*H_*T_*T_)
#define N_SCS ((long long)B_*H_*C_*C_)

#define O_h    0
#define O_q    (O_h    + N_BTC)
#define O_k    (O_q    + N_BTC)
#define O_v    (O_k    + N_BTC)
#define O_o    (O_v    + N_BTC)
#define O_x    (O_o    + N_BTC)
#define O_h2   (O_x    + N_BTC)
#define O_tout (O_h2   + N_BTC)
#define O_hs   (O_tout + N_BTC)
#define O_qs   (O_hs   + N_BTC)
#define O_ks   (O_qs   + N_BTC)
#define O_x2   (O_ks   + N_BTC)
#define O_h3   (O_x2   + N_BTC)
#define O_ff   (O_h3   + N_BTC)
#define O_scT  (O_ff   + N_FF)
#define O_scS  (O_scT  + N_SCT)
#define TOTAL_SCRATCH (O_scS + N_SCS)

__device__ float g_buf[TOTAL_SCRATCH];

// ============================== LayerNorm ==================================
__global__ void ln_kernel(const float* __restrict__ x, float* __restrict__ y,
                          const float* __restrict__ w, const float* __restrict__ b,
                          int L) {
    long long base = (long long)blockIdx.x * L;
    int tid = threadIdx.x;
    float s = 0.f, s2 = 0.f;
    for (int i = tid; i < L; i += 256) {
        float v = x[base + i];
        s += v; s2 += v * v;
    }
    __shared__ float sh[64];
    #pragma unroll
    for (int o = 16; o > 0; o >>= 1) {
        s  += __shfl_down_sync(0xffffffffu, s,  o);
        s2 += __shfl_down_sync(0xffffffffu, s2, o);
    }
    int warp = tid >> 5, lane = tid & 31;
    if (lane == 0) { sh[warp] = s; sh[warp + 32] = s2; }
    __syncthreads();
    if (tid == 0) {
        float ts = 0.f, ts2 = 0.f;
        for (int i = 0; i < 8; i++) { ts += sh[i]; ts2 += sh[32 + i]; }
        float m = ts / (float)L;
        float var = ts2 / (float)L - m * m;
        sh[0] = m;
        sh[1] = rsqrtf(var + 1e-6f);
    }
    __syncthreads();
    float m = sh[0], r = sh[1];
    for (int i = tid; i < L; i += 256)
        y[base + i] = (x[base + i] - m) * r * w[i] + b[i];
}

// ===================== Softmax (full row, length L<=512) ===================
__global__ void softmax_kernel(float* __restrict__ x, int L) {
    long long base = (long long)blockIdx.x * L;
    int tid = threadIdx.x;
    float v[2];
    #pragma unroll
    for (int c = 0; c < 2; c++) {
        int i = tid + c * 256;
        v[c] = (i < L) ? x[base + i] : -3.4e38f;
    }
    float mx = fmaxf(v[0], v[1]);
    __shared__ float sh[32];
    #pragma unroll
    for (int o = 16; o > 0; o >>= 1) mx = fmaxf(mx, __shfl_down_sync(0xffffffffu, mx, o));
    int warp = tid >> 5, lane = tid & 31;
    if (lane == 0) sh[warp] = mx;
    __syncthreads();
    if (tid == 0) {
        float m = sh[0];
        for (int i = 1; i < 8; i++) m = fmaxf(m, sh[i]);
        sh[0] = m;
    }
    __syncthreads();
    mx = sh[0];
    float sum = 0.f;
    #pragma unroll
    for (int c = 0; c < 2; c++) {
        int i = tid + c * 256;
        if (i < L) { v[c] = expf(v[c] - mx); sum += v[c]; }
    }
    __syncthreads();
    #pragma unroll
    for (int o = 16; o > 0; o >>= 1) sum += __shfl_down_sync(0xffffffffu, sum, o);
    if (lane == 0) sh[warp] = sum;
    __syncthreads();
    if (tid == 0) {
        float s = 0.f;
        for (int i = 0; i < 8; i++) s += sh[i];
        sh[0] = 1.f / s;
    }
    __syncthreads();
    float inv = sh[0];
    #pragma unroll
    for (int c = 0; c < 2; c++) {
        int i = tid + c * 256;
        if (i < L) x[base + i] = v[c] * inv;
    }
}

// ============== Causal softmax over rows of length T_ (=512) ===============
// Row index r = blockIdx.x, t = r % T_. Only elements i<=t participate;
// elements i>t are written as 0 (never read by the masked-score GEMM).
__global__ void softmax_causal_kernel(float* __restrict__ x) {
    long long base = (long long)blockIdx.x * T_;
    int t = blockIdx.x % T_;
    int tid = threadIdx.x;
    float v[2];
    bool act[2];
    #pragma unroll
    for (int c = 0; c < 2; c++) {
        int i = tid + c * 256;
        act[c] = (i <= t);
        v[c] = act[c] ? x[base + i] : -3.4e38f;
    }
    float mx = fmaxf(v[0], v[1]);
    __shared__ float sh[32];
    #pragma unroll
    for (int o = 16; o > 0; o >>= 1) mx = fmaxf(mx, __shfl_down_sync(0xffffffffu, mx, o));
    int warp = tid >> 5, lane = tid & 31;
    if (lane == 0) sh[warp] = mx;
    __syncthreads();
    if (tid == 0) {
        float m = sh[0];
        for (int i = 1; i < 8; i++) m = fmaxf(m, sh[i]);
        sh[0] = m;
    }
    __syncthreads();
    mx = sh[0];
    float sum = 0.f;
    #pragma unroll
    for (int c = 0; c < 2; c++) {
        if (act[c]) { v[c] = expf(v[c] - mx); sum += v[c]; }
    }
    __syncthreads();
    #pragma unroll
    for (int o = 16; o > 0; o >>= 1) sum += __shfl_down_sync(0xffffffffu, sum, o);
    if (lane == 0) sh[warp] = sum;
    __syncthreads();
    if (tid == 0) {
        float s = 0.f;
        for (int i = 0; i < 8; i++) s += sh[i];
        sh[0] = 1.f / s;
    }
    __syncthreads();
    float inv = sh[0];
    #pragma unroll
    for (int c = 0; c < 2; c++) {
        int i = tid + c * 256;
        x[base + i] = act[c] ? v[c] * inv : 0.f;
    }
}

// ============================ Mean over heads ==============================
__global__ void mean_heads_kernel(const float* __restrict__ sc, float* __restrict__ out) {
    long long idx = (long long)blockIdx.x * 256 + threadIdx.x;
    const long long NN = (long long)B_ * C_ * C_;
    if (idx >= NN) return;
    long long b = idx / (C_ * C_);
    long long r = idx % (C_ * C_);
    float s = 0.f;
    #pragma unroll
    for (int h = 0; h < H_; h++)
        s += sc[(b * H_ + h) * (long long)(C_ * C_) + r];
    out[idx] = s * 0.125f;
}

// ======================= Tensor-core GEMM (3x BF16) ========================
#define FLAG_RELU    1
#define FLAG_NT      4
#define FLAG_TRISKIP 8   // skip CTA tiles strictly above diagonal
#define FLAG_KTRI    16  // truncate K loop at row0+BM (lower-triangular A cols)

__device__ __forceinline__ void split2(float x0, float x1, unsigned &hi, unsigned &lo) {
    __nv_bfloat162 h = __floats2bfloat162_rn(x0, x1);
    float r0 = x0 - __bfloat162float(h.x);
    float r1 = x1 - __bfloat162float(h.y);
    __nv_bfloat162 l = __floats2bfloat162_rn(r0, r1);
    hi = *reinterpret_cast<unsigned*>(&h);
    lo = *reinterpret_cast<unsigned*>(&l);
}
__device__ __forceinline__ void mma16(float* c, const unsigned* a, const unsigned* b) {
    asm volatile("mma.sync.aligned.m16n8k16.row.col.f32.bf16.bf16.f32 "
        "{%0,%1,%2,%3}, {%4,%5,%6,%7}, {%8,%9}, {%0,%1,%2,%3};"
        : "+f"(c[0]), "+f"(c[1]), "+f"(c[2]), "+f"(c[3])
        : "r"(a[0]), "r"(a[1]), "r"(a[2]), "r"(a[3]), "r"(b[0]), "r"(b[1]));
}

// C = alpha*A@B' (+bias)(relu)(+res). Full tiles: M%128==0, N%BN==0, K%32==0.
template<int BN, int WN>
__global__ __launch_bounds__(128 * WN)
void mma_gemm(const float* __restrict__ A, int lda, long long sAo, long long sAi, int nInner,
              const float* __restrict__ Bm, int ldb, long long sBo, long long sBi,
              float* __restrict__ Cm, int ldc, long long sCo, long long sCi,
              int K, float alpha,
              const float* __restrict__ bias,
              const float* __restrict__ res, int ldres, long long sRo, long long sRi,
              int flags) {
    constexpr int BM = 128, BK = 32;
    constexpr int THREADS = 128 * WN;
    constexpr int WNT = BN / WN;
    constexpr int NJ  = WNT / 8;
    constexpr int BMP = BM + 8, BNP = BN + 8;

    if ((flags & FLAG_TRISKIP) && blockIdx.x > blockIdx.y) return;

    __shared__ __align__(16) unsigned Ah[16][BMP], Al[16][BMP];
    __shared__ __align__(16) unsigned Bh[16][BNP], Bl[16][BNP];

    int z  = blockIdx.z;
    int zo = z / nInner, zi = z % nInner;
    const float* Ab = A  + zo * sAo + zi * sAi;
    const float* Bb = Bm + zo * sBo + zi * sBi;
    float*       Cb = Cm + zo * sCo + zi * sCi;
    const float* Rb = res ? (res + zo * sRo + zi * sRi) : (const float*)0;

    int tid = threadIdx.x, lane = tid & 31, wid = tid >> 5;
    int wm = wid & 3, wn = wid >> 2;
    int row0 = blockIdx.y * BM;
    int col0 = blockIdx.x * BN;
    int r = lane >> 2, cq = lane & 3;

    int Keff = (flags & FLAG_KTRI) ? min(K, row0 + BM) : K;

    float acc[2][NJ][4];
    #pragma unroll
    for (int i = 0; i < 2; i++)
        #pragma unroll
        for (int j = 0; j < NJ; j++)
            #pragma unroll
            for (int e = 0; e < 4; e++) acc[i][j][e] = 0.f;

    for (int k0 = 0; k0 < Keff; k0 += BK) {
        // ---- A tile: [BM][BK] row-major -> k-pair packed hi/lo ----
        #pragma unroll
        for (int i = 0; i < (BM * 8) / THREADS; i++) {
            int idx = tid + i * THREADS;
            int m = idx >> 3;
            int k4 = idx & 7;
            float4 vA = *reinterpret_cast<const float4*>(
                Ab + (long long)(row0 + m) * lda + k0 + k4 * 4);
            unsigned h0, l0, h1, l1;
            split2(vA.x, vA.y, h0, l0);
            split2(vA.z, vA.w, h1, l1);
            Ah[k4 * 2][m] = h0; Al[k4 * 2][m] = l0;
            Ah[k4 * 2 + 1][m] = h1; Al[k4 * 2 + 1][m] = l1;
        }
        // ---- B tile ----
        if (flags & FLAG_NT) {
            #pragma unroll
            for (int i = 0; i < (BN * 8) / THREADS; i++) {
                int idx = tid + i * THREADS;
                int n = idx >> 3;
                int k4 = idx & 7;
                float4 vB = *reinterpret_cast<const float4*>(
                    Bb + (long long)(col0 + n) * ldb + k0 + k4 * 4);
                unsigned h0, l0, h1, l1;
                split2(vB.x, vB.y, h0, l0);
                split2(vB.z, vB.w, h1, l1);
                Bh[k4 * 2][n] = h0; Bl[k4 * 2][n] = l0;
                Bh[k4 * 2 + 1][n] = h1; Bl[k4 * 2 + 1][n] = l1;
            }
        } else {
            #pragma unroll
            for (int i = 0; i < (BN * 16) / THREADS; i++) {
                int idx = tid + i * THREADS;
                int kk2 = idx / BN;
                int n = idx % BN;
                const float* bp = Bb + (long long)(k0 + kk2 * 2) * ldb + col0 + n;
                float b0 = bp[0];
                float b1 = bp[ldb];
                unsigned h0, l0;
                split2(b0, b1, h0, l0);
                Bh[kk2][n] = h0; Bl[kk2][n] = l0;
            }
        }
        __syncthreads();

        #pragma unroll
        for (int k16 = 0; k16 < 2; k16++) {
            unsigned bh[NJ][2], bl[NJ][2];
            #pragma unroll
            for (int j = 0; j < NJ; j++) {
                int ncol = wn * WNT + j * 8 + r;
                bh[j][0] = Bh[k16 * 8 + cq][ncol];
                bh[j][1] = Bh[k16 * 8 + cq + 4][ncol];
                bl[j][0] = Bl[k16 * 8 + cq][ncol];
                bl[j][1] = Bl[k16 * 8 + cq + 4][ncol];
            }
            #pragma unroll
            for (int im = 0; im < 2; im++) {
                int mrow = wm * 32 + im * 16 + r;
                unsigned ah[4], al[4];
                ah[0] = Ah[k16 * 8 + cq][mrow];
                ah[1] = Ah[k16 * 8 + cq][mrow + 8];
                ah[2] = Ah[k16 * 8 + cq + 4][mrow];
                ah[3] = Ah[k16 * 8 + cq + 4][mrow + 8];
                al[0] = Al[k16 * 8 + cq][mrow];
                al[1] = Al[k16 * 8 + cq][mrow + 8];
                al[2] = Al[k16 * 8 + cq + 4][mrow];
                al[3] = Al[k16 * 8 + cq + 4][mrow + 8];
                #pragma unroll
                for (int j = 0; j < NJ; j++) {
                    mma16(acc[im][j], al, bh[j]);
                    mma16(acc[im][j], ah, bl[j]);
                    mma16(acc[im][j], ah, bh[j]);
                }
            }
        }
        __syncthreads();
    }

    // ---- epilogue ----
    #pragma unroll
    for (int im = 0; im < 2; im++) {
        #pragma unroll
        for (int j = 0; j < NJ; j++) {
            int gm0 = row0 + wm * 32 + im * 16 + r;
            int gn  = col0 + wn * WNT + j * 8 + cq * 2;
            #pragma unroll
            for (int half = 0; half < 2; half++) {
                int gm = gm0 + half * 8;
                float v0 = acc[im][j][half * 2 + 0] * alpha;
                float v1 = acc[im][j][half * 2 + 1] * alpha;
                if (bias) { v0 += bias[gn]; v1 += bias[gn + 1]; }
                if (flags & FLAG_RELU) { v0 = fmaxf(v0, 0.f); v1 = fmaxf(v1, 0.f); }
                if (Rb) {
                    const float* rp = Rb + (long long)gm * ldres + gn;
                    v0 += rp[0]; v1 += rp[1];
                }
                float2 st; st.x = v0; st.y = v1;
                *reinterpret_cast<float2*>(Cb + (long long)gm * ldc + gn) = st;
            }
        }
    }
}

static inline void gemm(const float* A, int lda, long long sAo, long long sAi,
                        const float* Bm, int ldb, long long sBo, long long sBi,
                        float* Cm, int ldc, long long sCo, long long sCi,
                        int M, int N, int K, int bOuter, int bInner,
                        float alpha, const float* bias,
                        const float* res, int ldres, long long sRo, long long sRi,
                        int flags) {
    if (N == 32) {
        dim3 grid(1, M / 128, bOuter * bInner);
        mma_gemm<32, 1><<<grid, 128>>>(A, lda, sAo, sAi, bInner,
                                       Bm, ldb, sBo, sBi, Cm, ldc, sCo, sCi,
                                       K, alpha, bias, res, ldres, sRo, sRi, flags);
    } else {
        dim3 grid(N / 128, M / 128, bOuter * bInner);
        mma_gemm<128, 2><<<grid, 256>>>(A, lda, sAo, sAi, bInner,
                                        Bm, ldb, sBo, sBi, Cm, ldc, sCo, sCi,
                                        K, alpha, bias, res, ldres, sRo, sRi, flags);
    }
}

// ================================ Launch ===================================
extern "C" void kernel_launch(void* const* d_in, const int* in_sizes, int n_in,
                              void* d_out, int out_size) {
    const float* x_T     = (const float*)d_in[0];
    const float* x_S     = (const float*)d_in[1];
    const float* Wq_t    = (const float*)d_in[2];
    const float* Wk_t    = (const float*)d_in[3];
    const float* Wv_t    = (const float*)d_in[4];
    const float* Wo      = (const float*)d_in[5];
    const float* Wq_s    = (const float*)d_in[6];
    const float* Wk_s    = (const float*)d_in[7];
    const float* ff1_w1  = (const float*)d_in[8];
    const float* ff1_b1  = (const float*)d_in[9];
    const float* ff1_w2  = (const float*)d_in[10];
    const float* ff1_b2  = (const float*)d_in[11];
    const float* ff2_w1  = (const float*)d_in[12];
    const float* ff2_b1  = (const float*)d_in[13];
    const float* ff2_w2  = (const float*)d_in[14];
    const float* ff2_b2  = (const float*)d_in[15];
    const float* t_ln1_w = (const float*)d_in[16];
    const float* t_ln1_b = (const float*)d_in[17];
    const float* t_ln2_w = (const float*)d_in[18];
    const float* t_ln2_b = (const float*)d_in[19];
    const float* s_ln1_w = (const float*)d_in[20];
    const float* s_ln1_b = (const float*)d_in[21];
    const float* fus_ln_w= (const float*)d_in[22];
    const float* fus_ln_b= (const float*)d_in[23];

    float* out = (float*)d_out;                 // [B,T,C]
    float* sw  = out + (size_t)N_BTC;           // [B,C,C]

    float* g = 0;
    cudaGetSymbolAddress((void**)&g, g_buf);
    float* h    = g + O_h;
    float* q    = g + O_q;
    float* k    = g + O_k;
    float* v    = g + O_v;
    float* ob   = g + O_o;
    float* xb   = g + O_x;
    float* h2   = g + O_h2;
    float* tout = g + O_tout;
    float* hs   = g + O_hs;
    float* qs   = g + O_qs;
    float* ks   = g + O_ks;
    float* x2b  = g + O_x2;
    float* h3   = g + O_h3;
    float* ffb  = g + O_ff;
    float* scT  = g + O_scT;
    float* scS  = g + O_scS;

    const long long TC = (long long)T_ * C_;
    const long long TT = (long long)T_ * T_;
    const long long CC = (long long)C_ * C_;

    // ---- temporal branch ----
    ln_kernel<<<B_ * T_, 256>>>(x_T, h, t_ln1_w, t_ln1_b, C_);

    gemm(h, C_, 0, 0, Wq_t, C_, 0, 0, q, C_, 0, 0, B_*T_, C_, C_, 1, 1,
         1.f, 0, 0, 0, 0, 0, FLAG_NT);
    gemm(h, C_, 0, 0, Wk_t, C_, 0, 0, k, C_, 0, 0, B_*T_, C_, C_, 1, 1,
         1.f, 0, 0, 0, 0, 0, FLAG_NT);
    gemm(h, C_, 0, 0, Wv_t, C_, 0, 0, v, C_, 0, 0, B_*T_, C_, C_, 1, 1,
         1.f, 0, 0, 0, 0, 0, FLAG_NT);

    // scores[b,h,t,s] = q.k / sqrt(32); tiles above diagonal skipped
    gemm(q, C_, TC, HST, k, C_, TC, HST,
         scT, T_, (long long)H_*TT, TT,
         T_, T_, HST, B_, H_,
         0.1767766952966369f, 0, 0, 0, 0, 0, FLAG_NT | FLAG_TRISKIP);

    softmax_causal_kernel<<<B_ * H_ * T_, 256>>>(scT);

    // o = att @ v  (NN, N=32), K truncated to row0+128 (att zero above diag)
    gemm(scT, T_, (long long)H_*TT, TT, v, C_, TC, HST,
         ob, C_, TC, HST,
         T_, HST, T_, B_, H_,
         1.f, 0, 0, 0, 0, 0, FLAG_KTRI);

    // x = x_T + o @ Wo^T
    gemm(ob, C_, 0, 0, Wo, C_, 0, 0, xb, C_, 0, 0, B_*T_, C_, C_, 1, 1,
         1.f, 0, x_T, C_, 0, 0, FLAG_NT);

    ln_kernel<<<B_ * T_, 256>>>(xb, h2, t_ln2_w, t_ln2_b, C_);

    gemm(h2, C_, 0, 0, ff1_w1, C_, 0, 0, ffb, 4*C_, 0, 0, B_*T_, 4*C_, C_, 1, 1,
         1.f, ff1_b1, 0, 0, 0, 0, FLAG_NT | FLAG_RELU);
    gemm(ffb, 4*C_, 0, 0, ff1_w2, 4*C_, 0, 0, tout, C_, 0, 0, B_*T_, C_, 4*C_, 1, 1,
         1.f, ff1_b2, xb, C_, 0, 0, FLAG_NT);

    // ---- spatial branch ----
    ln_kernel<<<B_ * C_, 256>>>(x_S, hs, s_ln1_w, s_ln1_b, T_);

    gemm(hs, T_, 0, 0, Wq_s, T_, 0, 0, qs, T_, 0, 0, B_*C_, T_, T_, 1, 1,
         1.f, 0, 0, 0, 0, 0, FLAG_NT);
    gemm(hs, T_, 0, 0, Wk_s, T_, 0, 0, ks, T_, 0, 0, B_*C_, T_, T_, 1, 1,
         1.f, 0, 0, 0, 0, 0, FLAG_NT);

    gemm(qs, T_, (long long)C_*T_, HSS, ks, T_, (long long)C_*T_, HSS,
         scS, C_, (long long)H_*CC, CC,
         C_, C_, HSS, B_, H_,
         0.125f, 0, 0, 0, 0, 0, FLAG_NT);

    softmax_kernel<<<B_ * H_ * C_, 256>>>(scS, C_);
    mean_heads_kernel<<<(B_*C_*C_ + 255) / 256, 256>>>(scS, sw);

    // ---- fusion ----
    gemm(tout, C_, TC, 0, sw, C_, CC, 0,
         x2b, C_, TC, 0,
         T_, C_, C_, B_, 1,
         1.f, 0, tout, C_, TC, 0, FLAG_NT);

    ln_kernel<<<B_ * T_, 256>>>(x2b, h3, fus_ln_w, fus_ln_b, C_);

    gemm(h3, C_, 0, 0, ff2_w1, C_, 0, 0, ffb, 4*C_, 0, 0, B_*T_, 4*C_, C_, 1, 1,
         1.f, ff2_b1, 0, 0, 0, 0, FLAG_NT | FLAG_RELU);
    gemm(ffb, 4*C_, 0, 0, ff2_w2, 4*C_, 0, 0, out, C_, 0, 0, B_*T_, C_, 4*C_, 1, 1,
         1.f, ff2_b2, x2b, C_, 0, 0, FLAG_NT);
}

// round 5
// speedup vs baseline: 2.2686x; 1.2132x over previous
#include <cuda_runtime.h>
#include <cuda_bf16.h>
#include <math.h>

#define B_  16
#define T_  512
#define C_  256
#define H_  8
#define HST 32
#define HSS 64

#define N_BTC (B_*T_*C_)
#define N_FF  (B_*T_*4*C_)
#define N_SCT ((long long)B_*H_*T_*T_)
#define N_SCS ((long long)B_*H_*C_*C_)

#define O_h    0
#define O_q    (O_h    + N_BTC)
#define O_k    (O_q    + N_BTC)
#define O_v    (O_k    + N_BTC)
#define O_o    (O_v    + N_BTC)
#define O_x    (O_o    + N_BTC)
#define O_h2   (O_x    + N_BTC)
#define O_tout (O_h2   + N_BTC)
#define O_hs   (O_tout + N_BTC)
#define O_qs   (O_hs   + N_BTC)
#define O_ks   (O_qs   + N_BTC)
#define O_x2   (O_ks   + N_BTC)
#define O_h3   (O_x2   + N_BTC)
#define O_ff   (O_h3   + N_BTC)
#define O_scT  (O_ff   + N_FF)
#define O_scS  (O_scT  + N_SCT)
#define TOTAL_SCRATCH (O_scS + N_SCS)

__device__ float g_buf[TOTAL_SCRATCH];

// ============================== LayerNorm ==================================
__global__ void ln_kernel(const float* __restrict__ x, float* __restrict__ y,
                          const float* __restrict__ w, const float* __restrict__ b,
                          int L) {
    long long base = (long long)blockIdx.x * L;
    int tid = threadIdx.x;
    float s = 0.f, s2 = 0.f;
    for (int i = tid; i < L; i += 256) {
        float v = x[base + i];
        s += v; s2 += v * v;
    }
    __shared__ float sh[64];
    #pragma unroll
    for (int o = 16; o > 0; o >>= 1) {
        s  += __shfl_down_sync(0xffffffffu, s,  o);
        s2 += __shfl_down_sync(0xffffffffu, s2, o);
    }
    int warp = tid >> 5, lane = tid & 31;
    if (lane == 0) { sh[warp] = s; sh[warp + 32] = s2; }
    __syncthreads();
    if (tid == 0) {
        float ts = 0.f, ts2 = 0.f;
        for (int i = 0; i < 8; i++) { ts += sh[i]; ts2 += sh[32 + i]; }
        float m = ts / (float)L;
        float var = ts2 / (float)L - m * m;
        sh[0] = m;
        sh[1] = rsqrtf(var + 1e-6f);
    }
    __syncthreads();
    float m = sh[0], r = sh[1];
    for (int i = tid; i < L; i += 256)
        y[base + i] = (x[base + i] - m) * r * w[i] + b[i];
}

// ===================== Softmax (full row, length L<=512) ===================
__global__ void softmax_kernel(float* __restrict__ x, int L) {
    long long base = (long long)blockIdx.x * L;
    int tid = threadIdx.x;
    float v[2];
    #pragma unroll
    for (int c = 0; c < 2; c++) {
        int i = tid + c * 256;
        v[c] = (i < L) ? x[base + i] : -3.4e38f;
    }
    float mx = fmaxf(v[0], v[1]);
    __shared__ float sh[32];
    #pragma unroll
    for (int o = 16; o > 0; o >>= 1) mx = fmaxf(mx, __shfl_down_sync(0xffffffffu, mx, o));
    int warp = tid >> 5, lane = tid & 31;
    if (lane == 0) sh[warp] = mx;
    __syncthreads();
    if (tid == 0) {
        float m = sh[0];
        for (int i = 1; i < 8; i++) m = fmaxf(m, sh[i]);
        sh[0] = m;
    }
    __syncthreads();
    mx = sh[0];
    float sum = 0.f;
    #pragma unroll
    for (int c = 0; c < 2; c++) {
        int i = tid + c * 256;
        if (i < L) { v[c] = expf(v[c] - mx); sum += v[c]; }
    }
    __syncthreads();
    #pragma unroll
    for (int o = 16; o > 0; o >>= 1) sum += __shfl_down_sync(0xffffffffu, sum, o);
    if (lane == 0) sh[warp] = sum;
    __syncthreads();
    if (tid == 0) {
        float s = 0.f;
        for (int i = 0; i < 8; i++) s += sh[i];
        sh[0] = 1.f / s;
    }
    __syncthreads();
    float inv = sh[0];
    #pragma unroll
    for (int c = 0; c < 2; c++) {
        int i = tid + c * 256;
        if (i < L) x[base + i] = v[c] * inv;
    }
}

// ============== Causal softmax over rows of length T_ (=512) ===============
__global__ void softmax_causal_kernel(float* __restrict__ x) {
    long long base = (long long)blockIdx.x * T_;
    int t = blockIdx.x % T_;
    int tid = threadIdx.x;
    float v[2];
    bool act[2];
    #pragma unroll
    for (int c = 0; c < 2; c++) {
        int i = tid + c * 256;
        act[c] = (i <= t);
        v[c] = act[c] ? x[base + i] : -3.4e38f;
    }
    float mx = fmaxf(v[0], v[1]);
    __shared__ float sh[32];
    #pragma unroll
    for (int o = 16; o > 0; o >>= 1) mx = fmaxf(mx, __shfl_down_sync(0xffffffffu, mx, o));
    int warp = tid >> 5, lane = tid & 31;
    if (lane == 0) sh[warp] = mx;
    __syncthreads();
    if (tid == 0) {
        float m = sh[0];
        for (int i = 1; i < 8; i++) m = fmaxf(m, sh[i]);
        sh[0] = m;
    }
    __syncthreads();
    mx = sh[0];
    float sum = 0.f;
    #pragma unroll
    for (int c = 0; c < 2; c++) {
        if (act[c]) { v[c] = expf(v[c] - mx); sum += v[c]; }
    }
    __syncthreads();
    #pragma unroll
    for (int o = 16; o > 0; o >>= 1) sum += __shfl_down_sync(0xffffffffu, sum, o);
    if (lane == 0) sh[warp] = sum;
    __syncthreads();
    if (tid == 0) {
        float s = 0.f;
        for (int i = 0; i < 8; i++) s += sh[i];
        sh[0] = 1.f / s;
    }
    __syncthreads();
    float inv = sh[0];
    #pragma unroll
    for (int c = 0; c < 2; c++) {
        int i = tid + c * 256;
        x[base + i] = act[c] ? v[c] * inv : 0.f;
    }
}

// ============================ Mean over heads ==============================
__global__ void mean_heads_kernel(const float* __restrict__ sc, float* __restrict__ out) {
    long long idx = (long long)blockIdx.x * 256 + threadIdx.x;
    const long long NN = (long long)B_ * C_ * C_;
    if (idx >= NN) return;
    long long b = idx / (C_ * C_);
    long long r = idx % (C_ * C_);
    float s = 0.f;
    #pragma unroll
    for (int h = 0; h < H_; h++)
        s += sc[(b * H_ + h) * (long long)(C_ * C_) + r];
    out[idx] = s * 0.125f;
}

// ================= Pipelined tensor-core GEMM (3x BF16) ====================
#define FLAG_RELU    1
#define FLAG_NT      4
#define FLAG_TRISKIP 8
#define FLAG_KTRI    16

__device__ __forceinline__ void split2(float x0, float x1, unsigned &hi, unsigned &lo) {
    __nv_bfloat162 h = __floats2bfloat162_rn(x0, x1);
    float r0 = x0 - __bfloat162float(h.x);
    float r1 = x1 - __bfloat162float(h.y);
    __nv_bfloat162 l = __floats2bfloat162_rn(r0, r1);
    hi = *reinterpret_cast<unsigned*>(&h);
    lo = *reinterpret_cast<unsigned*>(&l);
}
__device__ __forceinline__ void mma16(float* c, const unsigned* a, const unsigned* b) {
    asm volatile("mma.sync.aligned.m16n8k16.row.col.f32.bf16.bf16.f32 "
        "{%0,%1,%2,%3}, {%4,%5,%6,%7}, {%8,%9}, {%0,%1,%2,%3};"
        : "+f"(c[0]), "+f"(c[1]), "+f"(c[2]), "+f"(c[3])
        : "r"(a[0]), "r"(a[1]), "r"(a[2]), "r"(a[3]), "r"(b[0]), "r"(b[1]));
}
// swizzle: column c of k-pair row kp stored at c ^ ((kp>>1 & 7)<<2)
__device__ __forceinline__ int SWZ(int kp, int c) { return c ^ (((kp >> 1) & 7) << 2); }

template<int BN, int WN>
__global__ __launch_bounds__(128 * WN)
void mma_gemm(const float* __restrict__ A, int lda, long long sAo, long long sAi, int nInner,
              const float* __restrict__ Bm, int ldb, long long sBo, long long sBi,
              float* __restrict__ Cm, int ldc, long long sCo, long long sCi,
              int K, float alpha,
              const float* __restrict__ bias,
              const float* __restrict__ res, int ldres, long long sRo, long long sRi,
              int flags) {
    constexpr int BM = 128, BK = 32;
    constexpr int THREADS = 128 * WN;
    constexpr int WNT = BN / WN;
    constexpr int NJ  = WNT / 8;
    constexpr int BMP = BM + 8, BNP = BN + 8;
    constexpr int AH_O = 0;
    constexpr int AL_O = 16 * BMP;
    constexpr int BH_O = 32 * BMP;
    constexpr int BL_O = 32 * BMP + 16 * BNP;
    constexpr int STG  = 32 * (BMP + BNP);
    constexpr int AITER = (BM * 8) / THREADS;
    constexpr int BITER = (BN * 8) / THREADS;   // also = NN float4 count

    if ((flags & FLAG_TRISKIP) && blockIdx.x > blockIdx.y) return;

    extern __shared__ unsigned sm[];

    int z  = blockIdx.z;
    int zo = z / nInner, zi = z % nInner;
    const float* Ab = A  + zo * sAo + zi * sAi;
    const float* Bb = Bm + zo * sBo + zi * sBi;
    float*       Cb = Cm + zo * sCo + zi * sCi;
    const float* Rb = res ? (res + zo * sRo + zi * sRi) : (const float*)0;

    int tid = threadIdx.x, lane = tid & 31, wid = tid >> 5;
    int wm = wid & 3, wn = wid >> 2;
    int row0 = blockIdx.y * BM;
    int col0 = blockIdx.x * BN;
    int r = lane >> 2, cq = lane & 3;
    bool nt = (flags & FLAG_NT) != 0;

    int Keff = (flags & FLAG_KTRI) ? min(K, row0 + BM) : K;
    int nk = Keff / BK;

    float4 ra[AITER], rb[BITER];

    auto loadT = [&](int k0) {
        #pragma unroll
        for (int i = 0; i < AITER; i++) {
            int idx = tid + i * THREADS;
            int m = idx >> 3, k4 = idx & 7;
            ra[i] = *reinterpret_cast<const float4*>(
                Ab + (long long)(row0 + m) * lda + k0 + k4 * 4);
        }
        if (nt) {
            #pragma unroll
            for (int i = 0; i < BITER; i++) {
                int idx = tid + i * THREADS;
                int n = idx >> 3, k4 = idx & 7;
                rb[i] = *reinterpret_cast<const float4*>(
                    Bb + (long long)(col0 + n) * ldb + k0 + k4 * 4);
            }
        } else {
            #pragma unroll
            for (int i = 0; i < BITER; i++) {
                #pragma unroll
                for (int pz = 0; pz < 2; pz++) {
                    int pidx = tid + (i * 2 + pz) * THREADS;
                    int kk2 = pidx / BN;
                    int n = pidx % BN;
                    const float* bp = Bb + (long long)(k0 + kk2 * 2) * ldb + col0 + n;
                    float b0 = bp[0], b1 = bp[ldb];
                    if (pz == 0) { rb[i].x = b0; rb[i].y = b1; }
                    else         { rb[i].z = b0; rb[i].w = b1; }
                }
            }
        }
    };

    auto storeT = [&](int s) {
        unsigned* ah = sm + s * STG + AH_O;
        unsigned* al = sm + s * STG + AL_O;
        unsigned* bh = sm + s * STG + BH_O;
        unsigned* bl = sm + s * STG + BL_O;
        #pragma unroll
        for (int i = 0; i < AITER; i++) {
            int idx = tid + i * THREADS;
            int m = idx >> 3, k4 = idx & 7;
            int mc = m ^ (k4 << 2);
            unsigned h0, l0, h1, l1;
            split2(ra[i].x, ra[i].y, h0, l0);
            split2(ra[i].z, ra[i].w, h1, l1);
            ah[(k4 * 2) * BMP + mc] = h0;     al[(k4 * 2) * BMP + mc] = l0;
            ah[(k4 * 2 + 1) * BMP + mc] = h1; al[(k4 * 2 + 1) * BMP + mc] = l1;
        }
        if (nt) {
            #pragma unroll
            for (int i = 0; i < BITER; i++) {
                int idx = tid + i * THREADS;
                int n = idx >> 3, k4 = idx & 7;
                int nc = n ^ (k4 << 2);
                unsigned h0, l0, h1, l1;
                split2(rb[i].x, rb[i].y, h0, l0);
                split2(rb[i].z, rb[i].w, h1, l1);
                bh[(k4 * 2) * BNP + nc] = h0;     bl[(k4 * 2) * BNP + nc] = l0;
                bh[(k4 * 2 + 1) * BNP + nc] = h1; bl[(k4 * 2 + 1) * BNP + nc] = l1;
            }
        } else {
            #pragma unroll
            for (int i = 0; i < BITER; i++) {
                #pragma unroll
                for (int pz = 0; pz < 2; pz++) {
                    int pidx = tid + (i * 2 + pz) * THREADS;
                    int kk2 = pidx / BN;
                    int n = pidx % BN;
                    int nc = SWZ(kk2, n);
                    float b0 = pz ? rb[i].z : rb[i].x;
                    float b1 = pz ? rb[i].w : rb[i].y;
                    unsigned h0, l0;
                    split2(b0, b1, h0, l0);
                    bh[kk2 * BNP + nc] = h0;
                    bl[kk2 * BNP + nc] = l0;
                }
            }
        }
    };

    float acc[2][NJ][4];
    #pragma unroll
    for (int i = 0; i < 2; i++)
        #pragma unroll
        for (int j = 0; j < NJ; j++)
            #pragma unroll
            for (int e = 0; e < 4; e++) acc[i][j][e] = 0.f;

    auto compute = [&](int s) {
        const unsigned* ah = sm + s * STG + AH_O;
        const unsigned* al = sm + s * STG + AL_O;
        const unsigned* bhp = sm + s * STG + BH_O;
        const unsigned* blp = sm + s * STG + BL_O;
        #pragma unroll
        for (int k16 = 0; k16 < 2; k16++) {
            int kp0 = k16 * 8 + cq, kp1 = kp0 + 4;
            unsigned bf_h[NJ][2], bf_l[NJ][2];
            #pragma unroll
            for (int j = 0; j < NJ; j++) {
                int ncol = wn * WNT + j * 8 + r;
                bf_h[j][0] = bhp[kp0 * BNP + SWZ(kp0, ncol)];
                bf_h[j][1] = bhp[kp1 * BNP + SWZ(kp1, ncol)];
                bf_l[j][0] = blp[kp0 * BNP + SWZ(kp0, ncol)];
                bf_l[j][1] = blp[kp1 * BNP + SWZ(kp1, ncol)];
            }
            #pragma unroll
            for (int im = 0; im < 2; im++) {
                int mrow = wm * 32 + im * 16 + r;
                unsigned afh[4], afl[4];
                afh[0] = ah[kp0 * BMP + SWZ(kp0, mrow)];
                afh[1] = ah[kp0 * BMP + SWZ(kp0, mrow + 8)];
                afh[2] = ah[kp1 * BMP + SWZ(kp1, mrow)];
                afh[3] = ah[kp1 * BMP + SWZ(kp1, mrow + 8)];
                afl[0] = al[kp0 * BMP + SWZ(kp0, mrow)];
                afl[1] = al[kp0 * BMP + SWZ(kp0, mrow + 8)];
                afl[2] = al[kp1 * BMP + SWZ(kp1, mrow)];
                afl[3] = al[kp1 * BMP + SWZ(kp1, mrow + 8)];
                #pragma unroll
                for (int j = 0; j < NJ; j++) {
                    mma16(acc[im][j], afl, bf_h[j]);
                    mma16(acc[im][j], afh, bf_l[j]);
                    mma16(acc[im][j], afh, bf_h[j]);
                }
            }
        }
    };

    // ---- pipelined mainloop: 1 sync per iteration, double-buffered ----
    loadT(0);
    storeT(0);
    int p = 0;
    for (int kb = 0; kb < nk; kb++) {
        __syncthreads();
        bool more = (kb + 1) < nk;
        if (more) loadT((kb + 1) * BK);
        compute(p);
        if (more) storeT(1 - p);
        p ^= 1;
    }

    // ---- epilogue ----
    #pragma unroll
    for (int im = 0; im < 2; im++) {
        #pragma unroll
        for (int j = 0; j < NJ; j++) {
            int gm0 = row0 + wm * 32 + im * 16 + r;
            int gn  = col0 + wn * WNT + j * 8 + cq * 2;
            #pragma unroll
            for (int half = 0; half < 2; half++) {
                int gm = gm0 + half * 8;
                float v0 = acc[im][j][half * 2 + 0] * alpha;
                float v1 = acc[im][j][half * 2 + 1] * alpha;
                if (bias) { v0 += bias[gn]; v1 += bias[gn + 1]; }
                if (flags & FLAG_RELU) { v0 = fmaxf(v0, 0.f); v1 = fmaxf(v1, 0.f); }
                if (Rb) {
                    const float* rp = Rb + (long long)gm * ldres + gn;
                    v0 += rp[0]; v1 += rp[1];
                }
                float2 st; st.x = v0; st.y = v1;
                *reinterpret_cast<float2*>(Cb + (long long)gm * ldc + gn) = st;
            }
        }
    }
}

#define SMEM_BYTES(BN) (2 * 32 * ((128 + 8) + ((BN) + 8)) * 4)

static inline void gemm(const float* A, int lda, long long sAo, long long sAi,
                        const float* Bm, int ldb, long long sBo, long long sBi,
                        float* Cm, int ldc, long long sCo, long long sCi,
                        int M, int N, int K, int bOuter, int bInner,
                        float alpha, const float* bias,
                        const float* res, int ldres, long long sRo, long long sRi,
                        int flags) {
    if (N == 32) {
        dim3 grid(1, M / 128, bOuter * bInner);
        mma_gemm<32, 1><<<grid, 128, SMEM_BYTES(32)>>>(
            A, lda, sAo, sAi, bInner, Bm, ldb, sBo, sBi, Cm, ldc, sCo, sCi,
            K, alpha, bias, res, ldres, sRo, sRi, flags);
    } else {
        dim3 grid(N / 128, M / 128, bOuter * bInner);
        mma_gemm<128, 2><<<grid, 256, SMEM_BYTES(128)>>>(
            A, lda, sAo, sAi, bInner, Bm, ldb, sBo, sBi, Cm, ldc, sCo, sCi,
            K, alpha, bias, res, ldres, sRo, sRi, flags);
    }
}

// ================================ Launch ===================================
extern "C" void kernel_launch(void* const* d_in, const int* in_sizes, int n_in,
                              void* d_out, int out_size) {
    static int smem_cfg = 0;
    if (!smem_cfg) {
        cudaFuncSetAttribute((const void*)mma_gemm<128, 2>,
                             cudaFuncAttributeMaxDynamicSharedMemorySize, SMEM_BYTES(128));
        cudaFuncSetAttribute((const void*)mma_gemm<32, 1>,
                             cudaFuncAttributeMaxDynamicSharedMemorySize, SMEM_BYTES(32));
        smem_cfg = 1;
    }

    const float* x_T     = (const float*)d_in[0];
    const float* x_S     = (const float*)d_in[1];
    const float* Wq_t    = (const float*)d_in[2];
    const float* Wk_t    = (const float*)d_in[3];
    const float* Wv_t    = (const float*)d_in[4];
    const float* Wo      = (const float*)d_in[5];
    const float* Wq_s    = (const float*)d_in[6];
    const float* Wk_s    = (const float*)d_in[7];
    const float* ff1_w1  = (const float*)d_in[8];
    const float* ff1_b1  = (const float*)d_in[9];
    const float* ff1_w2  = (const float*)d_in[10];
    const float* ff1_b2  = (const float*)d_in[11];
    const float* ff2_w1  = (const float*)d_in[12];
    const float* ff2_b1  = (const float*)d_in[13];
    const float* ff2_w2  = (const float*)d_in[14];
    const float* ff2_b2  = (const float*)d_in[15];
    const float* t_ln1_w = (const float*)d_in[16];
    const float* t_ln1_b = (const float*)d_in[17];
    const float* t_ln2_w = (const float*)d_in[18];
    const float* t_ln2_b = (const float*)d_in[19];
    const float* s_ln1_w = (const float*)d_in[20];
    const float* s_ln1_b = (const float*)d_in[21];
    const float* fus_ln_w= (const float*)d_in[22];
    const float* fus_ln_b= (const float*)d_in[23];

    float* out = (float*)d_out;                 // [B,T,C]
    float* sw  = out + (size_t)N_BTC;           // [B,C,C]

    float* g = 0;
    cudaGetSymbolAddress((void**)&g, g_buf);
    float* h    = g + O_h;
    float* q    = g + O_q;
    float* k    = g + O_k;
    float* v    = g + O_v;
    float* ob   = g + O_o;
    float* xb   = g + O_x;
    float* h2   = g + O_h2;
    float* tout = g + O_tout;
    float* hs   = g + O_hs;
    float* qs   = g + O_qs;
    float* ks   = g + O_ks;
    float* x2b  = g + O_x2;
    float* h3   = g + O_h3;
    float* ffb  = g + O_ff;
    float* scT  = g + O_scT;
    float* scS  = g + O_scS;

    const long long TC = (long long)T_ * C_;
    const long long TT = (long long)T_ * T_;
    const long long CC = (long long)C_ * C_;

    // ---- temporal branch ----
    ln_kernel<<<B_ * T_, 256>>>(x_T, h, t_ln1_w, t_ln1_b, C_);

    gemm(h, C_, 0, 0, Wq_t, C_, 0, 0, q, C_, 0, 0, B_*T_, C_, C_, 1, 1,
         1.f, 0, 0, 0, 0, 0, FLAG_NT);
    gemm(h, C_, 0, 0, Wk_t, C_, 0, 0, k, C_, 0, 0, B_*T_, C_, C_, 1, 1,
         1.f, 0, 0, 0, 0, 0, FLAG_NT);
    gemm(h, C_, 0, 0, Wv_t, C_, 0, 0, v, C_, 0, 0, B_*T_, C_, C_, 1, 1,
         1.f, 0, 0, 0, 0, 0, FLAG_NT);

    gemm(q, C_, TC, HST, k, C_, TC, HST,
         scT, T_, (long long)H_*TT, TT,
         T_, T_, HST, B_, H_,
         0.1767766952966369f, 0, 0, 0, 0, 0, FLAG_NT | FLAG_TRISKIP);

    softmax_causal_kernel<<<B_ * H_ * T_, 256>>>(scT);

    gemm(scT, T_, (long long)H_*TT, TT, v, C_, TC, HST,
         ob, C_, TC, HST,
         T_, HST, T_, B_, H_,
         1.f, 0, 0, 0, 0, 0, FLAG_KTRI);

    gemm(ob, C_, 0, 0, Wo, C_, 0, 0, xb, C_, 0, 0, B_*T_, C_, C_, 1, 1,
         1.f, 0, x_T, C_, 0, 0, FLAG_NT);

    ln_kernel<<<B_ * T_, 256>>>(xb, h2, t_ln2_w, t_ln2_b, C_);

    gemm(h2, C_, 0, 0, ff1_w1, C_, 0, 0, ffb, 4*C_, 0, 0, B_*T_, 4*C_, C_, 1, 1,
         1.f, ff1_b1, 0, 0, 0, 0, FLAG_NT | FLAG_RELU);
    gemm(ffb, 4*C_, 0, 0, ff1_w2, 4*C_, 0, 0, tout, C_, 0, 0, B_*T_, C_, 4*C_, 1, 1,
         1.f, ff1_b2, xb, C_, 0, 0, FLAG_NT);

    // ---- spatial branch ----
    ln_kernel<<<B_ * C_, 256>>>(x_S, hs, s_ln1_w, s_ln1_b, T_);

    gemm(hs, T_, 0, 0, Wq_s, T_, 0, 0, qs, T_, 0, 0, B_*C_, T_, T_, 1, 1,
         1.f, 0, 0, 0, 0, 0, FLAG_NT);
    gemm(hs, T_, 0, 0, Wk_s, T_, 0, 0, ks, T_, 0, 0, B_*C_, T_, T_, 1, 1,
         1.f, 0, 0, 0, 0, 0, FLAG_NT);

    gemm(qs, T_, (long long)C_*T_, HSS, ks, T_, (long long)C_*T_, HSS,
         scS, C_, (long long)H_*CC, CC,
         C_, C_, HSS, B_, H_,
         0.125f, 0, 0, 0, 0, 0, FLAG_NT);

    softmax_kernel<<<B_ * H_ * C_, 256>>>(scS, C_);
    mean_heads_kernel<<<(B_*C_*C_ + 255) / 256, 256>>>(scS, sw);

    // ---- fusion ----
    gemm(tout, C_, TC, 0, sw, C_, CC, 0,
         x2b, C_, TC, 0,
         T_, C_, C_, B_, 1,
         1.f, 0, tout, C_, TC, 0, FLAG_NT);

    ln_kernel<<<B_ * T_, 256>>>(x2b, h3, fus_ln_w, fus_ln_b, C_);

    gemm(h3, C_, 0, 0, ff2_w1, C_, 0, 0, ffb, 4*C_, 0, 0, B_*T_, 4*C_, C_, 1, 1,
         1.f, ff2_b1, 0, 0, 0, 0, FLAG_NT | FLAG_RELU);
    gemm(ffb, 4*C_, 0, 0, ff2_w2, 4*C_, 0, 0, out, C_, 0, 0, B_*T_, C_, 4*C_, 1, 1,
         1.f, ff2_b2, x2b, C_, 0, 0, FLAG_NT);
}